// round 3
// baseline (speedup 1.0000x reference)
#include <cuda_runtime.h>
#include <math.h>

#define NB 32
#define NS 2048
#define NH 1024
#define NH4 (NH/4)       // 256 float4 per row
#define WPB 64           // warp-chunks per batch
#define ROWS (NS/WPB)    // 32 rows per warp

// ---- scratch (__device__ globals; no runtime allocation allowed) ----
__device__ float g_q[NB * NH];              // 128 KB
__device__ float g_energy[NB * NS];         // 256 KB (raw energies)
__device__ float g_m[NB * WPB];             // per-chunk running max
__device__ float g_z[NB * WPB];             // per-chunk partial sum
__device__ float g_ctx[NB * WPB * NH];      // 8 MB per-chunk context partials

// ============================================================================
// Kernel 1: q[b,o] = bias[o] + sum_i hidden[b,i] * W[o,i]
// grid (16, 4): blockIdx.x = 64-wide o block, blockIdx.y = 8-wide b block.
// ============================================================================
__global__ __launch_bounds__(256) void qkernel(const float* __restrict__ hidden,
                                               const float* __restrict__ W,
                                               const float* __restrict__ bias) {
    __shared__ float hid_s[8 * NH];          // 32 KB
    const int t = threadIdx.x;
    const int b0 = blockIdx.y * 8;

    const float4* hid4 = (const float4*)(hidden + (size_t)b0 * NH);
    float4* hs4 = (float4*)hid_s;
    #pragma unroll
    for (int k = 0; k < 8; k++) hs4[t + 256 * k] = hid4[t + 256 * k];
    __syncthreads();

    const int w = t >> 5, lane = t & 31;
    const float4* W4 = (const float4*)W;

    for (int oi = 0; oi < 8; oi++) {
        const int o = blockIdx.x * 64 + w * 8 + oi;
        float4 wr[8];
        #pragma unroll
        for (int p = 0; p < 8; p++) wr[p] = W4[(size_t)o * NH4 + lane + 32 * p];

        for (int bl = 0; bl < 8; bl++) {
            float acc = 0.f;
            #pragma unroll
            for (int p = 0; p < 8; p++) {
                float4 h4 = hs4[bl * NH4 + lane + 32 * p];
                acc += wr[p].x * h4.x + wr[p].y * h4.y
                     + wr[p].z * h4.z + wr[p].w * h4.w;
            }
            #pragma unroll
            for (int off = 16; off; off >>= 1)
                acc += __shfl_xor_sync(0xffffffffu, acc, off);
            if (lane == 0) g_q[(size_t)(b0 + bl) * NH + o] = acc + bias[o];
        }
    }
}

// ============================================================================
// Kernel 2: fused single-pass energy + online-softmax context accumulation.
// grid (8, 32): blockIdx.y = b, warp-chunk c = blockIdx.x*8 + warp (0..63).
// PAIR-ROW version: 2 rows per iteration -> 16 front-batched LDG.128 (MLP),
// two interleaved shuffle-reduce chains, and warp-uniform LAZY RESCALE
// (ctx only rescaled on a new prefix max, ~3x per chunk instead of 32x).
// ============================================================================
__global__ __launch_bounds__(256, 2) void mainkernel(const float* __restrict__ enc) {
    __shared__ float q_s[NH];                // 4 KB
    const int t = threadIdx.x, w = t >> 5, lane = t & 31;
    const int b = blockIdx.y;

    ((float4*)q_s)[t] = ((const float4*)g_q)[(size_t)b * NH4 + t];
    __syncthreads();

    const int c = blockIdx.x * 8 + w;
    const float4* enc4 = (const float4*)enc
                       + ((size_t)b * NS + (size_t)c * ROWS) * NH4;
    const float4* qs4 = (const float4*)q_s;

    float m = -INFINITY, z = 0.f;
    float4 ctx[8];
    #pragma unroll
    for (int p = 0; p < 8; p++) ctx[p] = make_float4(0.f, 0.f, 0.f, 0.f);

    for (int r = 0; r < ROWS; r += 2) {
        float4 v0[8], v1[8];
        #pragma unroll
        for (int p = 0; p < 8; p++) v0[p] = enc4[(size_t)r * NH4 + lane + 32 * p];
        #pragma unroll
        for (int p = 0; p < 8; p++) v1[p] = enc4[(size_t)(r + 1) * NH4 + lane + 32 * p];

        float e0 = 0.f, e1 = 0.f;
        #pragma unroll
        for (int p = 0; p < 8; p++) {
            float4 q4 = qs4[lane + 32 * p];
            e0 += v0[p].x * q4.x + v0[p].y * q4.y + v0[p].z * q4.z + v0[p].w * q4.w;
            e1 += v1[p].x * q4.x + v1[p].y * q4.y + v1[p].z * q4.z + v1[p].w * q4.w;
        }
        #pragma unroll
        for (int off = 16; off; off >>= 1) {
            e0 += __shfl_xor_sync(0xffffffffu, e0, off);
            e1 += __shfl_xor_sync(0xffffffffu, e1, off);
        }

        if (lane == 0)
            *(float2*)&g_energy[(size_t)b * NS + c * ROWS + r] = make_float2(e0, e1);

        // warp-uniform lazy rescale (e0/e1 identical across lanes post-butterfly)
        const float epk = fmaxf(e0, e1);
        if (epk > m) {
            const float sc = __expf(m - epk);    // 0 on first iteration
            z *= sc;
            #pragma unroll
            for (int p = 0; p < 8; p++) {
                ctx[p].x *= sc; ctx[p].y *= sc; ctx[p].z *= sc; ctx[p].w *= sc;
            }
            m = epk;
        }
        const float w0 = __expf(e0 - m);
        const float w1 = __expf(e1 - m);
        z += w0 + w1;
        #pragma unroll
        for (int p = 0; p < 8; p++) {
            ctx[p].x = fmaf(w0, v0[p].x, fmaf(w1, v1[p].x, ctx[p].x));
            ctx[p].y = fmaf(w0, v0[p].y, fmaf(w1, v1[p].y, ctx[p].y));
            ctx[p].z = fmaf(w0, v0[p].z, fmaf(w1, v1[p].z, ctx[p].z));
            ctx[p].w = fmaf(w0, v0[p].w, fmaf(w1, v1[p].w, ctx[p].w));
        }
    }

    const int idx = b * WPB + c;
    if (lane == 0) { g_m[idx] = m; g_z[idx] = z; }
    float4* out4 = (float4*)g_ctx + (size_t)idx * NH4;
    #pragma unroll
    for (int p = 0; p < 8; p++) out4[lane + 32 * p] = ctx[p];
}

// ============================================================================
// Kernel 3 (fused epilogue): grid (12, 32). b = blockIdx.y.
//   x in [0,4):  context slice  h = x*256 + t   (reduce 64 chunk partials)
//   x in [4,12): attention slice s = (x-4)*256+t (normalize stored energies)
// Each CTA recomputes the global max M and denominator Zt from g_m/g_z
// (64 values) -- cheap, and avoids any cross-kernel dependency.
// ============================================================================
__global__ __launch_bounds__(256) void epilogue(float* __restrict__ out) {
    __shared__ float ms[WPB], ws[WPB], zw[WPB];
    const int t = threadIdx.x;
    const int b = blockIdx.y;
    const int x = blockIdx.x;

    if (t < WPB) ms[t] = g_m[b * WPB + t];
    __syncthreads();
    float M = -INFINITY;
    #pragma unroll 8
    for (int cc = 0; cc < WPB; cc++) M = fmaxf(M, ms[cc]);
    if (t < WPB) {
        const float e = __expf(ms[t] - M);
        ws[t] = e;
        zw[t] = g_z[b * WPB + t] * e;
    }
    __syncthreads();
    float Zt = 0.f;
    #pragma unroll 8
    for (int cc = 0; cc < WPB; cc++) Zt += zw[cc];
    const float inv = 1.f / Zt;

    if (x < 4) {
        const int h = (x << 8) + t;
        float acc = 0.f;
        #pragma unroll 8
        for (int cc = 0; cc < WPB; cc++)
            acc += g_ctx[(size_t)(b * WPB + cc) * NH + h] * ws[cc];
        out[(size_t)b * NH + h] = acc * inv;
    } else {
        const int s = ((x - 4) << 8) + t;
        out[(size_t)NB * NH + (size_t)b * NS + s] =
            __expf(g_energy[(size_t)b * NS + s] - M) * inv;
    }
}

// ============================================================================
// Launch: inputs per metadata order: hidden, encoder_outputs, W_weight, W_bias.
// Output: context [32*1024] then attention [32*2048] (tuple order), fp32.
// ============================================================================
extern "C" void kernel_launch(void* const* d_in, const int* in_sizes, int n_in,
                              void* d_out, int out_size) {
    const float* hidden = (const float*)d_in[0];
    const float* enc    = (const float*)d_in[1];
    const float* W      = (const float*)d_in[2];
    const float* bias   = (const float*)d_in[3];
    float* out = (float*)d_out;

    qkernel<<<dim3(16, 4), 256>>>(hidden, W, bias);
    mainkernel<<<dim3(8, 32), 256>>>(enc);
    epilogue<<<dim3(12, 32), 256>>>(out);
}